// round 16
// baseline (speedup 1.0000x reference)
#include <cuda_runtime.h>
#include <cstdint>

#define N_EMBED 384
#define NE 8
#define THREADS 128
#define TOK_PER_BLK 128
#define KC 32
#define NCHUNK 12
#define NKSTEP 48                 // 384/8 k-steps
#define PITCH 36                  // staging pitch: STS.128 conflict-free AND (4g+t)%32 distinct for A-LDS

#define BFRAG_F2 (NKSTEP * 2 * 2 * 32)        // [ks][ntile][term][lane] = 6144 float2
#define BFRAG_BYTES (BFRAG_F2 * 8)            // 49152
#define SB_OFF  BFRAG_BYTES                   // 16 bias floats
#define XS_OFF  (BFRAG_BYTES + 64)
#define XS_BUF_FLOATS (TOK_PER_BLK * PITCH)   // 4608 floats = 18432 B
#define SMEM_TOTAL (XS_OFF + 2 * XS_BUF_FLOATS * 4)   // 86080 B -> 2 CTAs/SM
#define LP 17                                 // logits smem pitch (conflict-free)

#define TIE_TH 1e-4f                          // rescue threshold (>> 1e-6 MMA error)

__device__ __forceinline__ uint32_t smem_u32(const void* p) {
    return (uint32_t)__cvta_generic_to_shared(p);
}
__device__ __forceinline__ void cp16(uint32_t dst, const void* src, int pred) {
    asm volatile(
        "{ .reg .pred q; setp.ne.b32 q, %2, 0;\n\t"
        "@q cp.async.ca.shared.global [%0], [%1], 16; }"
        :: "r"(dst), "l"(src), "r"(pred));
}

#define MMA_TF32(acc, a0,a1,a2,a3, b0,b1)                                  \
    asm volatile("mma.sync.aligned.m16n8k8.row.col.f32.tf32.tf32.f32 "     \
        "{%0,%1,%2,%3}, {%4,%5,%6,%7}, {%8,%9}, {%0,%1,%2,%3};"            \
        : "+f"(acc[0]), "+f"(acc[1]), "+f"(acc[2]), "+f"(acc[3])           \
        : "r"(a0), "r"(a1), "r"(a2), "r"(a3), "r"(b0), "r"(b1))

// round-to-nearest fp32 -> tf32 (32-bit container, low 13 bits zero)
__device__ __forceinline__ uint32_t f2tf(float f) {
    uint32_t r; asm("cvt.rna.tf32.f32 %0, %1;" : "=r"(r) : "f"(f)); return r;
}

__global__ __launch_bounds__(THREADS, 2)
void noisy_topk_router_kernel(
    const float* __restrict__ x,        // [n_tok, 384]
    const float* __restrict__ noise,    // [n_tok, 8]
    const float* __restrict__ w_route,  // [8, 384]
    const float* __restrict__ b_route,  // [8]
    const float* __restrict__ w_noise,  // [8, 384]
    const float* __restrict__ b_noise,  // [8]
    float* __restrict__ out,
    int n_tok, int write_idx)
{
    extern __shared__ char smem[];
    float2* bfr = reinterpret_cast<float2*>(smem);           // B fragments (hi/lo tf32, frag order)
    float*  sb  = reinterpret_cast<float*>(smem + SB_OFF);   // biases: [0..7] route, [8..15] noise
    float*  xs  = reinterpret_cast<float*>(smem + XS_OFF);   // [2][128*36] staged x

    const int tid   = threadIdx.x;
    const int w     = tid >> 5;
    const int lane  = tid & 31;
    const int g     = lane >> 2;      // group id 0..7
    const int t     = lane & 3;       // thread-in-group 0..3
    const int t0    = blockIdx.x * TOK_PER_BLK;
    const int wbase = w * 32;         // warp's 32 token rows (2 m16 tiles)

    // ---- staging of x chunk c: 128 tokens x 32 floats (8 float4/row) ----
    auto stage = [&](int c) {
        float* dst = xs + (c & 1) * XS_BUF_FLOATS;
#pragma unroll
        for (int r = 0; r < 8; r++) {
            int idx = tid + r * THREADS;
            int tok = idx >> 3, q = idx & 7;
            const float* src = x + (size_t)(t0 + tok) * N_EMBED + c * KC + q * 4;
            cp16(smem_u32(dst + tok * PITCH + q * 4), src, (t0 + tok < n_tok) ? 1 : 0);
        }
        asm volatile("cp.async.commit_group;" ::: "memory");
    };

    stage(0);
    stage(1);

    // ---- precompute B fragments (hi/lo tf32, RN splits) in mma fragment order ----
    // elem (ks, nt, term, lane): b0 = term(W[n][k0]), b1 = term(W[n][k0+4]);
    // n = nt*8 + lane/4, k0 = ks*8 + lane%4
    for (int idx = tid; idx < BFRAG_F2; idx += THREADS) {
        int ln   = idx & 31;
        int rest = idx >> 5;
        int term = rest & 1;
        int nt   = (rest >> 1) & 1;
        int ks   = rest >> 2;
        int n    = nt * 8 + (ln >> 2);
        int k0   = ks * 8 + (ln & 3);
        const float* W = (n < 8) ? (w_route + n * N_EMBED) : (w_noise + (n - 8) * N_EMBED);
        float f0 = W[k0], f1 = W[k0 + 4];
        uint32_t h0 = f2tf(f0), h1 = f2tf(f1);
        uint32_t v0, v1;
        if (term) {
            v0 = f2tf(f0 - __uint_as_float(h0));
            v1 = f2tf(f1 - __uint_as_float(h1));
        } else {
            v0 = h0; v1 = h1;
        }
        bfr[idx] = make_float2(__uint_as_float(v0), __uint_as_float(v1));
    }
    if (tid < NE)            sb[tid] = b_route[tid];
    else if (tid < 2 * NE)   sb[tid] = b_noise[tid - NE];

    asm volatile("cp.async.wait_group 1;" ::: "memory");   // chunk 0 landed
    __syncthreads();                                       // bfr + sb + xs c0 visible

    float acc[2][2][4];
#pragma unroll
    for (int m = 0; m < 2; m++)
#pragma unroll
        for (int nt = 0; nt < 2; nt++)
#pragma unroll
            for (int i = 0; i < 4; i++) acc[m][nt][i] = 0.0f;

    for (int c = 0; c < NCHUNK; c++) {
        const float* buf = xs + (c & 1) * XS_BUF_FLOATS;
#pragma unroll
        for (int kk = 0; kk < 4; kk++) {
            const int ks = c * 4 + kk;
            float2 bh0 = bfr[((ks * 2 + 0) * 2 + 0) * 32 + lane];
            float2 bl0 = bfr[((ks * 2 + 0) * 2 + 1) * 32 + lane];
            float2 bh1 = bfr[((ks * 2 + 1) * 2 + 0) * 32 + lane];
            float2 bl1 = bfr[((ks * 2 + 1) * 2 + 1) * 32 + lane];
            uint32_t bh0x = __float_as_uint(bh0.x), bh0y = __float_as_uint(bh0.y);
            uint32_t bl0x = __float_as_uint(bl0.x), bl0y = __float_as_uint(bl0.y);
            uint32_t bh1x = __float_as_uint(bh1.x), bh1y = __float_as_uint(bh1.y);
            uint32_t bl1x = __float_as_uint(bl1.x), bl1y = __float_as_uint(bl1.y);
#pragma unroll
            for (int m = 0; m < 2; m++) {
                const float* p = buf + (wbase + m * 16 + g) * PITCH + kk * 8 + t;
                float f0 = p[0];
                float f1 = p[8 * PITCH];
                float f2 = p[4];
                float f3 = p[8 * PITCH + 4];
                uint32_t ah0 = f2tf(f0), ah1 = f2tf(f1), ah2 = f2tf(f2), ah3 = f2tf(f3);
                uint32_t al0 = f2tf(f0 - __uint_as_float(ah0));
                uint32_t al1 = f2tf(f1 - __uint_as_float(ah1));
                uint32_t al2 = f2tf(f2 - __uint_as_float(ah2));
                uint32_t al3 = f2tf(f3 - __uint_as_float(ah3));
                // 4-term: hi*hi + lo*hi + hi*lo + lo*lo
                MMA_TF32(acc[m][0], ah0, ah1, ah2, ah3, bh0x, bh0y);
                MMA_TF32(acc[m][0], al0, al1, al2, al3, bh0x, bh0y);
                MMA_TF32(acc[m][0], ah0, ah1, ah2, ah3, bl0x, bl0y);
                MMA_TF32(acc[m][0], al0, al1, al2, al3, bl0x, bl0y);
                MMA_TF32(acc[m][1], ah0, ah1, ah2, ah3, bh1x, bh1y);
                MMA_TF32(acc[m][1], al0, al1, al2, al3, bh1x, bh1y);
                MMA_TF32(acc[m][1], ah0, ah1, ah2, ah3, bl1x, bl1y);
                MMA_TF32(acc[m][1], al0, al1, al2, al3, bl1x, bl1y);
            }
        }
        __syncthreads();
        if (c + 2 < NCHUNK) stage(c + 2);
        else asm volatile("cp.async.commit_group;" ::: "memory");
        asm volatile("cp.async.wait_group 1;" ::: "memory");
        __syncthreads();
    }

    // ---- scatter C fragments to smem logits [128][LP] (reuse xs) ----
    float* L = xs;
#pragma unroll
    for (int m = 0; m < 2; m++) {
        int r = wbase + m * 16 + g;
#pragma unroll
        for (int nt = 0; nt < 2; nt++) {
            int cb = nt * 8 + 2 * t;
            L[r * LP + cb]           = acc[m][nt][0];
            L[r * LP + cb + 1]       = acc[m][nt][1];
            L[(r + 8) * LP + cb]     = acc[m][nt][2];
            L[(r + 8) * LP + cb + 1] = acc[m][nt][3];
        }
    }
    __syncthreads();

    // ---- finalize: thread == token ----
    int tok = t0 + tid;
    if (tok >= n_tok) return;

    const float4* np = reinterpret_cast<const float4*>(noise + (size_t)tok * NE);
    float4 nz0 = np[0], nz1 = np[1];
    float nz[NE] = {nz0.x, nz0.y, nz0.z, nz0.w, nz1.x, nz1.y, nz1.z, nz1.w};

    float v[NE];
#pragma unroll
    for (int e = 0; e < NE; e++) {
        float lg = L[tid * LP + e]     + sb[e];
        float nl = L[tid * LP + 8 + e] + sb[8 + e];
        float sp = fmaxf(nl, 0.0f) + log1pf(expf(-fabsf(nl)));   // jax softplus
        v[e] = lg + nz[e] * sp;
    }

    // top-2 (first occurrence) + third-best value for tie detection
    float v0 = v[0]; int i0 = 0;
#pragma unroll
    for (int e = 1; e < NE; e++)
        if (v[e] > v0) { v0 = v[e]; i0 = e; }
    float v1 = -3.402823466e+38f; int i1 = 0;
#pragma unroll
    for (int e = 0; e < NE; e++) {
        bool take = (e != i0) && (v[e] > v1);
        if (take) { v1 = v[e]; i1 = e; }
    }
    float v2 = -3.402823466e+38f;
#pragma unroll
    for (int e = 0; e < NE; e++)
        if (e != i0 && e != i1 && v[e] > v2) v2 = v[e];

    // ---- exact-rescue: near-tie tokens get full fp32 scalar recompute ----
    if ((v0 - v1 < TIE_TH) || (v1 - v2 < TIE_TH)) {
        float lg[NE], nl[NE];
#pragma unroll
        for (int e = 0; e < NE; e++) { lg[e] = sb[e]; nl[e] = sb[8 + e]; }
        const float* xr = x + (size_t)tok * N_EMBED;
        for (int d = 0; d < N_EMBED; d += 4) {
            float4 xv = *reinterpret_cast<const float4*>(xr + d);
#pragma unroll
            for (int e = 0; e < NE; e++) {
                const float* wr = w_route + e * N_EMBED + d;
                const float* wn = w_noise + e * N_EMBED + d;
                lg[e] = fmaf(xv.x, wr[0], lg[e]);
                lg[e] = fmaf(xv.y, wr[1], lg[e]);
                lg[e] = fmaf(xv.z, wr[2], lg[e]);
                lg[e] = fmaf(xv.w, wr[3], lg[e]);
                nl[e] = fmaf(xv.x, wn[0], nl[e]);
                nl[e] = fmaf(xv.y, wn[1], nl[e]);
                nl[e] = fmaf(xv.z, wn[2], nl[e]);
                nl[e] = fmaf(xv.w, wn[3], nl[e]);
            }
        }
#pragma unroll
        for (int e = 0; e < NE; e++) {
            float sp = fmaxf(nl[e], 0.0f) + log1pf(expf(-fabsf(nl[e])));
            v[e] = lg[e] + nz[e] * sp;
        }
        v0 = v[0]; i0 = 0;
#pragma unroll
        for (int e = 1; e < NE; e++)
            if (v[e] > v0) { v0 = v[e]; i0 = e; }
        v1 = -3.402823466e+38f; i1 = 0;
#pragma unroll
        for (int e = 0; e < NE; e++) {
            bool take = (e != i0) && (v[e] > v1);
            if (take) { v1 = v[e]; i1 = e; }
        }
    }

    float e1 = expf(v1 - v0);
    float inv = 1.0f / (1.0f + e1);
    float p0 = inv, p1 = e1 * inv;

    float o[NE];
#pragma unroll
    for (int e = 0; e < NE; e++)
        o[e] = (e == i0) ? p0 : ((e == i1) ? p1 : 0.0f);

    float4* op = reinterpret_cast<float4*>(out + (size_t)tok * NE);
    op[0] = make_float4(o[0], o[1], o[2], o[3]);
    op[1] = make_float4(o[4], o[5], o[6], o[7]);

    if (write_idx) {
        float2* ip = reinterpret_cast<float2*>(out + (size_t)n_tok * NE);
        ip[tok] = make_float2((float)i0, (float)i1);
    }
}

extern "C" void kernel_launch(void* const* d_in, const int* in_sizes, int n_in,
                              void* d_out, int out_size) {
    const float* x       = (const float*)d_in[0];
    const float* noise   = (const float*)d_in[1];
    const float* w_route = (const float*)d_in[2];
    const float* b_route = (const float*)d_in[3];
    const float* w_noise = (const float*)d_in[4];
    const float* b_noise = (const float*)d_in[5];
    float* out = (float*)d_out;

    int n_tok = in_sizes[0] / N_EMBED;
    int write_idx = (out_size >= n_tok * NE + n_tok * 2) ? 1 : 0;

    cudaFuncSetAttribute(noisy_topk_router_kernel,
                         cudaFuncAttributeMaxDynamicSharedMemorySize, SMEM_TOTAL);

    int grid = (n_tok + TOK_PER_BLK - 1) / TOK_PER_BLK;   // 512
    noisy_topk_router_kernel<<<grid, THREADS, SMEM_TOTAL>>>(
        x, noise, w_route, b_route, w_noise, b_noise, out, n_tok, write_idx);
}